// round 15
// baseline (speedup 1.0000x reference)
#include <cuda_runtime.h>
#include <math.h>
#include <stdint.h>

#define BSZ    2
#define SEQ    2048
#define DMODEL 2048
#define NHEADS 16
#define HDIM   128
#define BH     (BSZ*NHEADS)
#define MROWS  (BSZ*SEQ)

// ---- scratch ----
__device__ float g_q[BH*SEQ*HDIM];
__device__ float g_k[BH*SEQ*HDIM];
__device__ float g_v[BH*SEQ*HDIM];
__device__ float g_attn[MROWS*DMODEL];
__device__ float g_cos[SEQ*64];
__device__ float g_sin[SEQ*64];

__device__ __forceinline__ float to_tf32(float x) {
    float y;
    asm("cvt.rna.tf32.f32 %0, %1;" : "=f"(y) : "f"(x));
    return y;
}
__device__ __forceinline__ void mma_tf32(float* c, const uint32_t* a, const uint32_t* b) {
    asm volatile(
        "mma.sync.aligned.m16n8k8.row.col.f32.tf32.tf32.f32 "
        "{%0,%1,%2,%3}, {%4,%5,%6,%7}, {%8,%9}, {%0,%1,%2,%3};"
        : "+f"(c[0]), "+f"(c[1]), "+f"(c[2]), "+f"(c[3])
        : "r"(a[0]), "r"(a[1]), "r"(a[2]), "r"(a[3]), "r"(b[0]), "r"(b[1]));
}
__device__ __forceinline__ float4 tf32x4(float4 v) {
    v.x = to_tf32(v.x); v.y = to_tf32(v.y); v.z = to_tf32(v.z); v.w = to_tf32(v.w);
    return v;
}

// =================== RoPE ===================
__global__ void rope_cache_kernel() {
    int idx = blockIdx.x * blockDim.x + threadIdx.x;
    if (idx >= SEQ * 64) return;
    int pos = idx >> 6, j = idx & 63;
    double e    = (double)(2 * j) / 128.0;
    double invf = pow(10000.0, -e);
    double ang  = (double)pos * invf;
    g_cos[idx] = (float)cos(ang);
    g_sin[idx] = (float)sin(ang);
}
// outputs rounded to tf32 so flash can skip fill-time conversion
__global__ void rope_apply_kernel() {
    int idx = blockIdx.x * blockDim.x + threadIdx.x;
    if (idx >= BH * SEQ * 64) return;
    int j = idx & 63, row = idx >> 6, s = row & (SEQ - 1);
    float c = g_cos[s * 64 + j], sn = g_sin[s * 64 + j];
    float* qp = g_q + (size_t)row * HDIM;
    float* kp = g_k + (size_t)row * HDIM;
    float q1 = qp[j], q2 = qp[j + 64];
    qp[j]      = to_tf32(q1 * c - q2 * sn);
    qp[j + 64] = to_tf32(q2 * c + q1 * sn);
    float k1 = kp[j], k2 = kp[j + 64];
    kp[j]      = to_tf32(k1 * c - k2 * sn);
    kp[j + 64] = to_tf32(k2 * c + k1 * sn);
}

// =================== TF32 GEMM: vector-fragment smem, double-buffered (R12, best) ===================
// mode 1 epilogue rounds outputs to tf32 (V consumed directly by flash; Q/K re-rounded by RoPE).
#define GEMM_K  DMODEL
#define KSTAGES (GEMM_K / 16)    // 128
#define ATS 132
#define BTS 66
#define A_STAGE (16*ATS)         // 2112 words
#define B_STAGE (32*BTS)         // 2112 words

__global__ __launch_bounds__(256, 2)
void tf32_gemm(const float* __restrict__ A,
               const float* __restrict__ B0, const float* __restrict__ B1,
               const float* __restrict__ B2,
               float* __restrict__ C0, float* __restrict__ C1, float* __restrict__ C2,
               int mode)
{
    __shared__ float As[2][A_STAGE];
    __shared__ float Bs[2][B_STAGE];

    const int z = blockIdx.z;
    const float* B = (z == 0) ? B0 : (z == 1) ? B1 : B2;
    float* C       = (z == 0) ? C0 : (z == 1) ? C1 : C2;

    const int tid  = threadIdx.x;
    const int wid  = tid >> 5;
    const int lane = tid & 31;
    const int bm = blockIdx.y * 128;
    const int bn = blockIdx.x * 128;
    const int wm = wid >> 2;
    const int wn = wid & 3;
    const int swzL = lane ^ ((lane >> 3) & 3);

    int aWord[2], bWord[2], cSw[2];
    const float4* Ap[2];
    const float4* Bp[2];
#pragma unroll
    for (int i = 0; i < 2; i++) {
        int f = i * 256 + tid;
        int row = f >> 2, c4 = f & 3;
        int kb = c4 >> 1, kh = c4 & 1;
        int g = row & 7, hi = (row >> 3) & 1;
        int mt = row >> 4, nt = row >> 3;
        cSw[i] = (g >> 1) & 3;
        aWord[i] = (mt * 2 + kb) * ATS + 16 * g + (hi + 2 * kh);
        bWord[i] = (nt * 2 + kb) * BTS + 8 * g + kh;
        Ap[i] = (const float4*)(A + (size_t)(bm + row) * GEMM_K) + c4;
        Bp[i] = (const float4*)(B + (size_t)(bn + row) * GEMM_K) + c4;
    }

    float acc[4][4][4];
#pragma unroll
    for (int mt = 0; mt < 4; mt++)
#pragma unroll
        for (int nt = 0; nt < 4; nt++)
#pragma unroll
            for (int e = 0; e < 4; e++) acc[mt][nt][e] = 0.f;

    float4 pa[2], pb[2];
#pragma unroll
    for (int i = 0; i < 2; i++) { pa[i] = Ap[i][0]; pb[i] = Bp[i][0]; }
#pragma unroll
    for (int i = 0; i < 2; i++) {
        float4 a = tf32x4(pa[i]), b = tf32x4(pb[i]);
        float va[4] = {a.x, a.y, a.z, a.w};
        float vb[4] = {b.x, b.y, b.z, b.w};
#pragma unroll
        for (int j = 0; j < 4; j++) {
            As[0][aWord[i] + 4 * (j ^ cSw[i])] = va[j];
            Bs[0][bWord[i] + 2 * (j ^ cSw[i])] = vb[j];
        }
    }
#pragma unroll
    for (int i = 0; i < 2; i++) { pa[i] = Ap[i][4]; pb[i] = Bp[i][4]; }
    __syncthreads();

    const int aT0 = (wm * 4) * 2 * ATS + 4 * swzL;
    const int bT0 = (wn * 4) * 2 * BTS + 2 * swzL;

#pragma unroll 1
    for (int ks = 0; ks < KSTAGES; ks++) {
        const int buf = ks & 1;
        if (ks + 1 < KSTAGES) {
#pragma unroll
            for (int i = 0; i < 2; i++) {
                float4 a = tf32x4(pa[i]), b = tf32x4(pb[i]);
                float va[4] = {a.x, a.y, a.z, a.w};
                float vb[4] = {b.x, b.y, b.z, b.w};
#pragma unroll
                for (int j = 0; j < 4; j++) {
                    As[buf ^ 1][aWord[i] + 4 * (j ^ cSw[i])] = va[j];
                    Bs[buf ^ 1][bWord[i] + 2 * (j ^ cSw[i])] = vb[j];
                }
            }
        }
#pragma unroll
        for (int kb = 0; kb < 2; kb++) {
            uint32_t a[4][4], b[4][2];
#pragma unroll
            for (int mt = 0; mt < 4; mt++)
                *(uint4*)a[mt] = *(const uint4*)&As[buf][aT0 + (mt * 2 + kb) * ATS];
#pragma unroll
            for (int nt = 0; nt < 4; nt++)
                *(uint2*)b[nt] = *(const uint2*)&Bs[buf][bT0 + (nt * 2 + kb) * BTS];
#pragma unroll
            for (int mt = 0; mt < 4; mt++)
#pragma unroll
                for (int nt = 0; nt < 4; nt++)
                    mma_tf32(acc[mt][nt], a[mt], b[nt]);
        }
        if (ks + 2 < KSTAGES) {
#pragma unroll
            for (int i = 0; i < 2; i++) {
                pa[i] = Ap[i][(ks + 2) * 4];
                pb[i] = Bp[i][(ks + 2) * 4];
            }
        }
        __syncthreads();
    }

    const int g = lane >> 2, tig = lane & 3;
#pragma unroll
    for (int mt = 0; mt < 4; mt++) {
#pragma unroll
        for (int nt = 0; nt < 4; nt++) {
            int row = bm + wm * 64 + mt * 16 + g;
            int col = bn + wn * 32 + nt * 8 + tig * 2;
            float* c0;
            size_t rstride;
            float e0 = acc[mt][nt][0], e1 = acc[mt][nt][1];
            float e2 = acc[mt][nt][2], e3 = acc[mt][nt][3];
            if (mode == 0) {
                c0 = C + (size_t)row * DMODEL + col;
                rstride = DMODEL;
            } else {
                int b = row >> 11, s = row & (SEQ - 1);
                int h = col >> 7, hd = col & 127;
                c0 = C + (((size_t)(b * NHEADS + h)) * SEQ + s) * HDIM + hd;
                rstride = HDIM;
                e0 = to_tf32(e0); e1 = to_tf32(e1);
                e2 = to_tf32(e2); e3 = to_tf32(e3);
            }
            *(float2*)c0 = make_float2(e0, e1);
            *(float2*)(c0 + 8 * rstride) = make_float2(e2, e3);
        }
    }
}

// =================== Flash attention: 128-thread CTAs, 64-q tiles, 2 CTAs/SM ===================
// Inputs q,k,v pre-rounded to tf32 — fill does NO conversion.
// Output attn rounded to tf32 (O-proj fill CVT then idempotent).
#define FKTS 72
#define FKE  36
#define FVTS 577
#define FOFF_V 9216
#define FLASH_SMEM_BYTES ((9216 + 9248) * 4)   // 73856 B per CTA; 2 CTAs/SM

__global__ __launch_bounds__(128, 2)
void flash_fwd(const float* __restrict__ Qg, const float* __restrict__ Kg,
               const float* __restrict__ Vg, float* __restrict__ Og)
{
    extern __shared__ float smf[];
    float* Kf = smf;
    float* Vf = smf + FOFF_V;

    const int tid  = threadIdx.x;
    const int wid  = tid >> 5;            // 0..3
    const int lane = tid & 31;
    const int g4 = lane >> 2, tig = lane & 3;
    const int qt = (int)(gridDim.x - 1 - blockIdx.x);   // heavy CTAs first
    const int bh = blockIdx.y;
    const int m0 = qt * 64;
    const int warpRow = m0 + wid * 16;
    const size_t base = (size_t)bh * SEQ * HDIM;
    const float scale = 0.08838834764831845f;

    // ---- Q a-fragments in registers (scale folded, re-rounded) ----
    uint32_t qa[16][4];
    {
        const float* qA = Qg + base + (size_t)(warpRow + g4) * HDIM;
        const float* qB = qA + 8 * HDIM;
#pragma unroll
        for (int kt = 0; kt < 16; kt++) {
            qa[kt][0] = __float_as_uint(to_tf32(qA[kt * 8 + tig] * scale));
            qa[kt][1] = __float_as_uint(to_tf32(qB[kt * 8 + tig] * scale));
            qa[kt][2] = __float_as_uint(to_tf32(qA[kt * 8 + tig + 4] * scale));
            qa[kt][3] = __float_as_uint(to_tf32(qB[kt * 8 + tig + 4] * scale));
        }
    }

    float o[16][4];
#pragma unroll
    for (int nt = 0; nt < 16; nt++)
#pragma unroll
        for (int e = 0; e < 4; e++) o[nt][e] = 0.f;
    float mA = -1e30f, mB = -1e30f, lA = 0.f, lB = 0.f;

    const int ntiles = qt + 1;
    for (int t = 0; t < ntiles; t++) {
        const int n0 = t * 64;
        __syncthreads();

        // ---- fill K (permuted n) and V (true k order); no conversion ----
#pragma unroll
        for (int i = 0; i < 16; i++) {
            int row = i * 4 + wid;          // warp-uniform kv row 0..63
            int gt = row & 7;
            int gp = (gt < 4) ? 2 * gt : 2 * (gt - 4) + 1;
            {
                float4 kv = *(const float4*)(Kg + base + (size_t)(n0 + row) * HDIM + lane * 4);
                int ntg = row >> 3, kt = lane >> 1, kh = lane & 1;
                *(float4*)&Kf[(ntg * 16 + kt) * FKTS + kh * FKE + gp * 4] = kv;
            }
            {
                float4 vv = *(const float4*)(Vg + base + (size_t)(n0 + row) * HDIM + lane * 4);
                int ktv = row >> 3, ev = gt >> 2, q4 = gt & 3;
                float vj[4] = {vv.x, vv.y, vv.z, vv.w};
#pragma unroll
                for (int j = 0; j < 4; j++) {
                    int n = 4 * lane + j;
                    Vf[(n >> 3) * FVTS + ktv * FKTS + ev * FKE + (n & 7) * 4 + q4] = vj[j];
                }
            }
        }
        __syncthreads();

        // ---- S = Q K^T ----
        float s[8][4];
#pragma unroll
        for (int nt = 0; nt < 8; nt++)
#pragma unroll
            for (int e = 0; e < 4; e++) s[nt][e] = 0.f;
#pragma unroll
        for (int kt = 0; kt < 16; kt++) {
            uint32_t b[8][2];
#pragma unroll
            for (int nt = 0; nt < 8; nt++) {
                b[nt][0] = __float_as_uint(Kf[(nt * 16 + kt) * FKTS + lane]);
                b[nt][1] = __float_as_uint(Kf[(nt * 16 + kt) * FKTS + FKE + lane]);
            }
#pragma unroll
            for (int nt = 0; nt < 8; nt++)
                mma_tf32(s[nt], qa[kt], b[nt]);
        }

        // ---- causal mask (true kv indices) ----
        const int qrA = warpRow + g4, qrB = qrA + 8;
        if (n0 + 63 > warpRow) {
#pragma unroll
            for (int nt = 0; nt < 8; nt++) {
                int kv0 = n0 + nt * 8 + tig, kv1 = kv0 + 4;
                if (kv0 > qrA) s[nt][0] = -1e30f;
                if (kv1 > qrA) s[nt][1] = -1e30f;
                if (kv0 > qrB) s[nt][2] = -1e30f;
                if (kv1 > qrB) s[nt][3] = -1e30f;
            }
        }

        // ---- online softmax ----
        float mxA = -1e30f, mxB = -1e30f;
#pragma unroll
        for (int nt = 0; nt < 8; nt++) {
            mxA = fmaxf(mxA, fmaxf(s[nt][0], s[nt][1]));
            mxB = fmaxf(mxB, fmaxf(s[nt][2], s[nt][3]));
        }
        mxA = fmaxf(mxA, __shfl_xor_sync(0xFFFFFFFFu, mxA, 1));
        mxA = fmaxf(mxA, __shfl_xor_sync(0xFFFFFFFFu, mxA, 2));
        mxB = fmaxf(mxB, __shfl_xor_sync(0xFFFFFFFFu, mxB, 1));
        mxB = fmaxf(mxB, __shfl_xor_sync(0xFFFFFFFFu, mxB, 2));
        float mnA = fmaxf(mA, mxA), mnB = fmaxf(mB, mxB);
        float aAl = __expf(mA - mnA), aBl = __expf(mB - mnB);
        mA = mnA; mB = mnB;
#pragma unroll
        for (int nt = 0; nt < 16; nt++) {
            o[nt][0] *= aAl; o[nt][1] *= aAl;
            o[nt][2] *= aBl; o[nt][3] *= aBl;
        }
        float sumA = 0.f, sumB = 0.f;
#pragma unroll
        for (int nt = 0; nt < 8; nt++) {
            float p0 = to_tf32(__expf(s[nt][0] - mA));
            float p1 = to_tf32(__expf(s[nt][1] - mA));
            float p2 = to_tf32(__expf(s[nt][2] - mB));
            float p3 = to_tf32(__expf(s[nt][3] - mB));
            s[nt][0] = p0; s[nt][1] = p1; s[nt][2] = p2; s[nt][3] = p3;
            sumA += p0 + p1; sumB += p2 + p3;
        }
        lA = lA * aAl + sumA;
        lB = lB * aBl + sumB;

        // ---- O += P V  (P a-frag = {s0, s2, s1, s3}) ----
#pragma unroll
        for (int kp = 0; kp < 8; kp++) {
            uint32_t a[4] = { __float_as_uint(s[kp][0]), __float_as_uint(s[kp][2]),
                              __float_as_uint(s[kp][1]), __float_as_uint(s[kp][3]) };
            uint32_t b[16][2];
#pragma unroll
            for (int nt = 0; nt < 16; nt++) {
                b[nt][0] = __float_as_uint(Vf[nt * FVTS + kp * FKTS + lane]);
                b[nt][1] = __float_as_uint(Vf[nt * FVTS + kp * FKTS + FKE + lane]);
            }
#pragma unroll
            for (int nt = 0; nt < 16; nt++)
                mma_tf32(o[nt], a, b[nt]);
        }
    }

    // ---- epilogue (rounded to tf32 for the O-projection) ----
    lA += __shfl_xor_sync(0xFFFFFFFFu, lA, 1);
    lA += __shfl_xor_sync(0xFFFFFFFFu, lA, 2);
    lB += __shfl_xor_sync(0xFFFFFFFFu, lB, 1);
    lB += __shfl_xor_sync(0xFFFFFFFFu, lB, 2);
    float invA = 1.f / lA, invB = 1.f / lB;
    const int b_ = bh >> 4, h = bh & 15;
    const int srA = warpRow + g4, srB = srA + 8;
    float* opA = Og + ((size_t)(b_ * SEQ + srA)) * DMODEL + h * HDIM;
    float* opB = Og + ((size_t)(b_ * SEQ + srB)) * DMODEL + h * HDIM;
#pragma unroll
    for (int nt = 0; nt < 16; nt++) {
        *(float2*)(opA + nt * 8 + 2 * tig) =
            make_float2(to_tf32(o[nt][0] * invA), to_tf32(o[nt][1] * invA));
        *(float2*)(opB + nt * 8 + 2 * tig) =
            make_float2(to_tf32(o[nt][2] * invB), to_tf32(o[nt][3] * invB));
    }
}

// =================== launch ===================
extern "C" void kernel_launch(void* const* d_in, const int* in_sizes, int n_in,
                              void* d_out, int out_size)
{
    (void)in_sizes; (void)n_in; (void)out_size;
    const float* hidden = (const float*)d_in[0];
    const float* Wq = (const float*)d_in[3];
    const float* Wk = (const float*)d_in[4];
    const float* Wv = (const float*)d_in[5];
    const float* Wo = (const float*)d_in[6];
    float* out = (float*)d_out;

    float *q, *k, *v, *attn;
    cudaGetSymbolAddress((void**)&q,    g_q);
    cudaGetSymbolAddress((void**)&k,    g_k);
    cudaGetSymbolAddress((void**)&v,    g_v);
    cudaGetSymbolAddress((void**)&attn, g_attn);

    cudaFuncSetAttribute(flash_fwd, cudaFuncAttributeMaxDynamicSharedMemorySize,
                         FLASH_SMEM_BYTES);

    rope_cache_kernel<<<(SEQ * 64 + 255) / 256, 256>>>();

    dim3 gQKV(DMODEL / 128, MROWS / 128, 3);
    tf32_gemm<<<gQKV, 256>>>(hidden, Wq, Wk, Wv, q, k, v, 1);

    rope_apply_kernel<<<(BH * SEQ * 64 + 255) / 256, 256>>>();

    flash_fwd<<<dim3(SEQ / 64, BH), 128, FLASH_SMEM_BYTES>>>(q, k, v, attn);

    dim3 gO(DMODEL / 128, MROWS / 128, 1);
    tf32_gemm<<<gO, 256>>>(attn, Wo, Wo, Wo, out, out, out, 0);
}

// round 16
// speedup vs baseline: 1.3362x; 1.3362x over previous
#include <cuda_runtime.h>
#include <cuda_fp16.h>
#include <math.h>
#include <stdint.h>

#define BSZ    2
#define SEQ    2048
#define DMODEL 2048
#define NHEADS 16
#define HDIM   128
#define BH     (BSZ*NHEADS)
#define MROWS  (BSZ*SEQ)

// ---- scratch ----
__device__ float g_q[BH*SEQ*HDIM];
__device__ float g_k[BH*SEQ*HDIM];
__device__ float g_v[BH*SEQ*HDIM];
__device__ float g_attn[MROWS*DMODEL];
__device__ float g_cos[SEQ*64];
__device__ float g_sin[SEQ*64];

__device__ __forceinline__ float to_tf32(float x) {
    float y;
    asm("cvt.rna.tf32.f32 %0, %1;" : "=f"(y) : "f"(x));
    return y;
}
__device__ __forceinline__ void mma_tf32(float* c, const uint32_t* a, const uint32_t* b) {
    asm volatile(
        "mma.sync.aligned.m16n8k8.row.col.f32.tf32.tf32.f32 "
        "{%0,%1,%2,%3}, {%4,%5,%6,%7}, {%8,%9}, {%0,%1,%2,%3};"
        : "+f"(c[0]), "+f"(c[1]), "+f"(c[2]), "+f"(c[3])
        : "r"(a[0]), "r"(a[1]), "r"(a[2]), "r"(a[3]), "r"(b[0]), "r"(b[1]));
}
__device__ __forceinline__ void mma_f16(float* c, const uint32_t* a, const uint32_t* b) {
    asm volatile(
        "mma.sync.aligned.m16n8k16.row.col.f32.f16.f16.f32 "
        "{%0,%1,%2,%3}, {%4,%5,%6,%7}, {%8,%9}, {%0,%1,%2,%3};"
        : "+f"(c[0]), "+f"(c[1]), "+f"(c[2]), "+f"(c[3])
        : "r"(a[0]), "r"(a[1]), "r"(a[2]), "r"(a[3]), "r"(b[0]), "r"(b[1]));
}
__device__ __forceinline__ uint32_t pack_h2(float x, float y) {
    __half2 h = __floats2half2_rn(x, y);
    return *(uint32_t*)&h;
}

// =================== RoPE ===================
__global__ void rope_cache_kernel() {
    int idx = blockIdx.x * blockDim.x + threadIdx.x;
    if (idx >= SEQ * 64) return;
    int pos = idx >> 6, j = idx & 63;
    double e    = (double)(2 * j) / 128.0;
    double invf = pow(10000.0, -e);
    double ang  = (double)pos * invf;
    g_cos[idx] = (float)cos(ang);
    g_sin[idx] = (float)sin(ang);
}
// outputs rounded to tf32 so flash can skip fill-time conversion
__global__ void rope_apply_kernel() {
    int idx = blockIdx.x * blockDim.x + threadIdx.x;
    if (idx >= BH * SEQ * 64) return;
    int j = idx & 63, row = idx >> 6, s = row & (SEQ - 1);
    float c = g_cos[s * 64 + j], sn = g_sin[s * 64 + j];
    float* qp = g_q + (size_t)row * HDIM;
    float* kp = g_k + (size_t)row * HDIM;
    float q1 = qp[j], q2 = qp[j + 64];
    qp[j]      = to_tf32(q1 * c - q2 * sn);
    qp[j + 64] = to_tf32(q2 * c + q1 * sn);
    float k1 = kp[j], k2 = kp[j + 64];
    kp[j]      = to_tf32(k1 * c - k2 * sn);
    kp[j + 64] = to_tf32(k2 * c + k1 * sn);
}

// =================== FP16 GEMM: packed-half fragment smem, double-buffered ===================
// C[m,n] = sum_k A[m,k]*B[n,k]. 128x128 CTA tile, K stage 16 (one m16n8k16 k-block),
// 8 warps (2m x 4n), warp tile 64x32. Structure cloned from the proven tf32 R12 kernel.
// A tiles (8, one per mt): word = mt*132 + 4*(4g + (tig^((g>>1)&3))) + (hi + 2*khalf)
//   word = packed {A[row][2p], A[row][2p+1]}, p = 2*khalf*2 + ... (p = pair index = tig + 4*khalf)
//   consumer: LDS.128 at mt*132 + 4*swzL -> a-frag {a0,a1,a2,a3}  (conflict-free)
// B tiles (16, one per nt): word = nt*66 + 2*(4gn + (tig^((gn>>1)&3))) + e
//   consumer: LDS.64 at nt*66 + 2*swzL -> b-frag {b0,b1}          (conflict-free)
#define GEMM_K  DMODEL
#define KSTAGES (GEMM_K / 16)    // 128
#define ATS 132
#define BTS 66
#define A_STAGE (8*ATS)          // 1056 words
#define B_STAGE (16*BTS)         // 1056 words

__global__ __launch_bounds__(256, 2)
void fp16_gemm(const float* __restrict__ A,
               const float* __restrict__ B0, const float* __restrict__ B1,
               const float* __restrict__ B2,
               float* __restrict__ C0, float* __restrict__ C1, float* __restrict__ C2,
               int mode)
{
    __shared__ uint32_t As[2][A_STAGE];
    __shared__ uint32_t Bs[2][B_STAGE];

    const int z = blockIdx.z;
    const float* B = (z == 0) ? B0 : (z == 1) ? B1 : B2;
    float* C       = (z == 0) ? C0 : (z == 1) ? C1 : C2;

    const int tid  = threadIdx.x;
    const int wid  = tid >> 5;
    const int lane = tid & 31;
    const int bm = blockIdx.y * 128;
    const int bn = blockIdx.x * 128;
    const int wm = wid >> 2;
    const int wn = wid & 3;
    const int swzL = lane ^ ((lane >> 3) & 3);

    // fill mapping: 2 float4 chunks per operand per thread per stage.
    // float4 at (row, k=4c4..4c4+3) -> 2 packed words (pairs p=2c4, 2c4+1).
    int aWord[2][2], bWord[2][2];
    const float4* Ap[2];
    const float4* Bp[2];
#pragma unroll
    for (int i = 0; i < 2; i++) {
        int f = i * 256 + tid;
        int row = f >> 2, c4 = f & 3;
        int g = row & 7, hi = (row >> 3) & 1;
        int mt = row >> 4, nt = row >> 3;
        int sw = (g >> 1) & 3;
        int khalf = c4 >> 1;            // pair k-half (0: k<8, 1: k>=8)
#pragma unroll
        for (int d = 0; d < 2; d++) {
            int p = 2 * c4 + d;         // pair index 0..7
            int tig = p & 3;
            aWord[i][d] = mt * ATS + 4 * (4 * g + (tig ^ sw)) + (hi + 2 * khalf);
            bWord[i][d] = nt * BTS + 2 * (4 * g + (tig ^ sw)) + khalf;
        }
        Ap[i] = (const float4*)(A + (size_t)(bm + row) * GEMM_K) + c4;
        Bp[i] = (const float4*)(B + (size_t)(bn + row) * GEMM_K) + c4;
    }

    float acc[4][4][4];
#pragma unroll
    for (int mt = 0; mt < 4; mt++)
#pragma unroll
        for (int nt = 0; nt < 4; nt++)
#pragma unroll
            for (int e = 0; e < 4; e++) acc[mt][nt][e] = 0.f;

    float4 pa[2], pb[2];
#pragma unroll
    for (int i = 0; i < 2; i++) { pa[i] = Ap[i][0]; pb[i] = Bp[i][0]; }
#pragma unroll
    for (int i = 0; i < 2; i++) {
        As[0][aWord[i][0]] = pack_h2(pa[i].x, pa[i].y);
        As[0][aWord[i][1]] = pack_h2(pa[i].z, pa[i].w);
        Bs[0][bWord[i][0]] = pack_h2(pb[i].x, pb[i].y);
        Bs[0][bWord[i][1]] = pack_h2(pb[i].z, pb[i].w);
    }
#pragma unroll
    for (int i = 0; i < 2; i++) { pa[i] = Ap[i][4]; pb[i] = Bp[i][4]; }
    __syncthreads();

    const int aT0 = (wm * 4) * ATS + 4 * swzL;
    const int bT0 = (wn * 4) * BTS + 2 * swzL;

#pragma unroll 1
    for (int ks = 0; ks < KSTAGES; ks++) {
        const int buf = ks & 1;
        if (ks + 1 < KSTAGES) {
#pragma unroll
            for (int i = 0; i < 2; i++) {
                As[buf ^ 1][aWord[i][0]] = pack_h2(pa[i].x, pa[i].y);
                As[buf ^ 1][aWord[i][1]] = pack_h2(pa[i].z, pa[i].w);
                Bs[buf ^ 1][bWord[i][0]] = pack_h2(pb[i].x, pb[i].y);
                Bs[buf ^ 1][bWord[i][1]] = pack_h2(pb[i].z, pb[i].w);
            }
        }
        {
            uint32_t a[4][4], b[4][2];
#pragma unroll
            for (int mt = 0; mt < 4; mt++)
                *(uint4*)a[mt] = *(const uint4*)&As[buf][aT0 + mt * ATS];
#pragma unroll
            for (int nt = 0; nt < 4; nt++)
                *(uint2*)b[nt] = *(const uint2*)&Bs[buf][bT0 + nt * BTS];
#pragma unroll
            for (int mt = 0; mt < 4; mt++)
#pragma unroll
                for (int nt = 0; nt < 4; nt++)
                    mma_f16(acc[mt][nt], a[mt], b[nt]);
        }
        if (ks + 2 < KSTAGES) {
#pragma unroll
            for (int i = 0; i < 2; i++) {
                pa[i] = Ap[i][(ks + 2) * 4];
                pb[i] = Bp[i][(ks + 2) * 4];
            }
        }
        __syncthreads();
    }

    const int g = lane >> 2, tig = lane & 3;
#pragma unroll
    for (int mt = 0; mt < 4; mt++) {
#pragma unroll
        for (int nt = 0; nt < 4; nt++) {
            int row = bm + wm * 64 + mt * 16 + g;
            int col = bn + wn * 32 + nt * 8 + tig * 2;
            float* c0;
            size_t rstride;
            float e0 = acc[mt][nt][0], e1 = acc[mt][nt][1];
            float e2 = acc[mt][nt][2], e3 = acc[mt][nt][3];
            if (mode == 0) {
                c0 = C + (size_t)row * DMODEL + col;
                rstride = DMODEL;
            } else {
                int b = row >> 11, s = row & (SEQ - 1);
                int h = col >> 7, hd = col & 127;
                c0 = C + (((size_t)(b * NHEADS + h)) * SEQ + s) * HDIM + hd;
                rstride = HDIM;
                e0 = to_tf32(e0); e1 = to_tf32(e1);
                e2 = to_tf32(e2); e3 = to_tf32(e3);
            }
            *(float2*)c0 = make_float2(e0, e1);
            *(float2*)(c0 + 8 * rstride) = make_float2(e2, e3);
        }
    }
}

// =================== Flash attention: 128-thread CTAs, 64-q tiles, 2 CTAs/SM (R14, tf32) ===================
// Inputs q,k,v pre-rounded to tf32 — fill does NO conversion.
// Output attn rounded to tf32 (fp16 O-proj quantizes further at fill).
#define FKTS 72
#define FKE  36
#define FVTS 577
#define FOFF_V 9216
#define FLASH_SMEM_BYTES ((9216 + 9248) * 4)   // 73856 B per CTA; 2 CTAs/SM

__global__ __launch_bounds__(128, 2)
void flash_fwd(const float* __restrict__ Qg, const float* __restrict__ Kg,
               const float* __restrict__ Vg, float* __restrict__ Og)
{
    extern __shared__ float smf[];
    float* Kf = smf;
    float* Vf = smf + FOFF_V;

    const int tid  = threadIdx.x;
    const int wid  = tid >> 5;            // 0..3
    const int lane = tid & 31;
    const int g4 = lane >> 2, tig = lane & 3;
    const int qt = (int)(gridDim.x - 1 - blockIdx.x);   // heavy CTAs first
    const int bh = blockIdx.y;
    const int m0 = qt * 64;
    const int warpRow = m0 + wid * 16;
    const size_t base = (size_t)bh * SEQ * HDIM;
    const float scale = 0.08838834764831845f;

    // ---- Q a-fragments in registers (scale folded, re-rounded) ----
    uint32_t qa[16][4];
    {
        const float* qA = Qg + base + (size_t)(warpRow + g4) * HDIM;
        const float* qB = qA + 8 * HDIM;
#pragma unroll
        for (int kt = 0; kt < 16; kt++) {
            qa[kt][0] = __float_as_uint(to_tf32(qA[kt * 8 + tig] * scale));
            qa[kt][1] = __float_as_uint(to_tf32(qB[kt * 8 + tig] * scale));
            qa[kt][2] = __float_as_uint(to_tf32(qA[kt * 8 + tig + 4] * scale));
            qa[kt][3] = __float_as_uint(to_tf32(qB[kt * 8 + tig + 4] * scale));
        }
    }

    float o[16][4];
#pragma unroll
    for (int nt = 0; nt < 16; nt++)
#pragma unroll
        for (int e = 0; e < 4; e++) o[nt][e] = 0.f;
    float mA = -1e30f, mB = -1e30f, lA = 0.f, lB = 0.f;

    const int ntiles = qt + 1;
    for (int t = 0; t < ntiles; t++) {
        const int n0 = t * 64;
        __syncthreads();

        // ---- fill K (permuted n) and V (true k order); no conversion ----
#pragma unroll
        for (int i = 0; i < 16; i++) {
            int row = i * 4 + wid;          // warp-uniform kv row 0..63
            int gt = row & 7;
            int gp = (gt < 4) ? 2 * gt : 2 * (gt - 4) + 1;
            {
                float4 kv = *(const float4*)(Kg + base + (size_t)(n0 + row) * HDIM + lane * 4);
                int ntg = row >> 3, kt = lane >> 1, kh = lane & 1;
                *(float4*)&Kf[(ntg * 16 + kt) * FKTS + kh * FKE + gp * 4] = kv;
            }
            {
                float4 vv = *(const float4*)(Vg + base + (size_t)(n0 + row) * HDIM + lane * 4);
                int ktv = row >> 3, ev = gt >> 2, q4 = gt & 3;
                float vj[4] = {vv.x, vv.y, vv.z, vv.w};
#pragma unroll
                for (int j = 0; j < 4; j++) {
                    int n = 4 * lane + j;
                    Vf[(n >> 3) * FVTS + ktv * FKTS + ev * FKE + (n & 7) * 4 + q4] = vj[j];
                }
            }
        }
        __syncthreads();

        // ---- S = Q K^T ----
        float s[8][4];
#pragma unroll
        for (int nt = 0; nt < 8; nt++)
#pragma unroll
            for (int e = 0; e < 4; e++) s[nt][e] = 0.f;
#pragma unroll
        for (int kt = 0; kt < 16; kt++) {
            uint32_t b[8][2];
#pragma unroll
            for (int nt = 0; nt < 8; nt++) {
                b[nt][0] = __float_as_uint(Kf[(nt * 16 + kt) * FKTS + lane]);
                b[nt][1] = __float_as_uint(Kf[(nt * 16 + kt) * FKTS + FKE + lane]);
            }
#pragma unroll
            for (int nt = 0; nt < 8; nt++)
                mma_tf32(s[nt], qa[kt], b[nt]);
        }

        // ---- causal mask (true kv indices) ----
        const int qrA = warpRow + g4, qrB = qrA + 8;
        if (n0 + 63 > warpRow) {
#pragma unroll
            for (int nt = 0; nt < 8; nt++) {
                int kv0 = n0 + nt * 8 + tig, kv1 = kv0 + 4;
                if (kv0 > qrA) s[nt][0] = -1e30f;
                if (kv1 > qrA) s[nt][1] = -1e30f;
                if (kv0 > qrB) s[nt][2] = -1e30f;
                if (kv1 > qrB) s[nt][3] = -1e30f;
            }
        }

        // ---- online softmax ----
        float mxA = -1e30f, mxB = -1e30f;
#pragma unroll
        for (int nt = 0; nt < 8; nt++) {
            mxA = fmaxf(mxA, fmaxf(s[nt][0], s[nt][1]));
            mxB = fmaxf(mxB, fmaxf(s[nt][2], s[nt][3]));
        }
        mxA = fmaxf(mxA, __shfl_xor_sync(0xFFFFFFFFu, mxA, 1));
        mxA = fmaxf(mxA, __shfl_xor_sync(0xFFFFFFFFu, mxA, 2));
        mxB = fmaxf(mxB, __shfl_xor_sync(0xFFFFFFFFu, mxB, 1));
        mxB = fmaxf(mxB, __shfl_xor_sync(0xFFFFFFFFu, mxB, 2));
        float mnA = fmaxf(mA, mxA), mnB = fmaxf(mB, mxB);
        float aAl = __expf(mA - mnA), aBl = __expf(mB - mnB);
        mA = mnA; mB = mnB;
#pragma unroll
        for (int nt = 0; nt < 16; nt++) {
            o[nt][0] *= aAl; o[nt][1] *= aAl;
            o[nt][2] *= aBl; o[nt][3] *= aBl;
        }
        float sumA = 0.f, sumB = 0.f;
#pragma unroll
        for (int nt = 0; nt < 8; nt++) {
            float p0 = to_tf32(__expf(s[nt][0] - mA));
            float p1 = to_tf32(__expf(s[nt][1] - mA));
            float p2 = to_tf32(__expf(s[nt][2] - mB));
            float p3 = to_tf32(__expf(s[nt][3] - mB));
            s[nt][0] = p0; s[nt][1] = p1; s[nt][2] = p2; s[nt][3] = p3;
            sumA += p0 + p1; sumB += p2 + p3;
        }
        lA = lA * aAl + sumA;
        lB = lB * aBl + sumB;

        // ---- O += P V  (P a-frag = {s0, s2, s1, s3}) ----
#pragma unroll
        for (int kp = 0; kp < 8; kp++) {
            uint32_t a[4] = { __float_as_uint(s[kp][0]), __float_as_uint(s[kp][2]),
                              __float_as_uint(s[kp][1]), __float_as_uint(s[kp][3]) };
            uint32_t b[16][2];
#pragma unroll
            for (int nt = 0; nt < 16; nt++) {
                b[nt][0] = __float_as_uint(Vf[nt * FVTS + kp * FKTS + lane]);
                b[nt][1] = __float_as_uint(Vf[nt * FVTS + kp * FKTS + FKE + lane]);
            }
#pragma unroll
            for (int nt = 0; nt < 16; nt++)
                mma_tf32(o[nt], a, b[nt]);
        }
    }

    // ---- epilogue (rounded to tf32 for the O-projection) ----
    lA += __shfl_xor_sync(0xFFFFFFFFu, lA, 1);
    lA += __shfl_xor_sync(0xFFFFFFFFu, lA, 2);
    lB += __shfl_xor_sync(0xFFFFFFFFu, lB, 1);
    lB += __shfl_xor_sync(0xFFFFFFFFu, lB, 2);
    float invA = 1.f / lA, invB = 1.f / lB;
    const int b_ = bh >> 4, h = bh & 15;
    const int srA = warpRow + g4, srB = srA + 8;
    float* opA = Og + ((size_t)(b_ * SEQ + srA)) * DMODEL + h * HDIM;
    float* opB = Og + ((size_t)(b_ * SEQ + srB)) * DMODEL + h * HDIM;
#pragma unroll
    for (int nt = 0; nt < 16; nt++) {
        *(float2*)(opA + nt * 8 + 2 * tig) =
            make_float2(to_tf32(o[nt][0] * invA), to_tf32(o[nt][1] * invA));
        *(float2*)(opB + nt * 8 + 2 * tig) =
            make_float2(to_tf32(o[nt][2] * invB), to_tf32(o[nt][3] * invB));
    }
}

// =================== launch ===================
extern "C" void kernel_launch(void* const* d_in, const int* in_sizes, int n_in,
                              void* d_out, int out_size)
{
    (void)in_sizes; (void)n_in; (void)out_size;
    const float* hidden = (const float*)d_in[0];
    const float* Wq = (const float*)d_in[3];
    const float* Wk = (const float*)d_in[4];
    const float* Wv = (const float*)d_in[5];
    const float* Wo = (const float*)d_in[6];
    float* out = (float*)d_out;

    float *q, *k, *v, *attn;
    cudaGetSymbolAddress((void**)&q,    g_q);
    cudaGetSymbolAddress((void**)&k,    g_k);
    cudaGetSymbolAddress((void**)&v,    g_v);
    cudaGetSymbolAddress((void**)&attn, g_attn);

    cudaFuncSetAttribute(flash_fwd, cudaFuncAttributeMaxDynamicSharedMemorySize,
                         FLASH_SMEM_BYTES);

    rope_cache_kernel<<<(SEQ * 64 + 255) / 256, 256>>>();

    dim3 gQKV(DMODEL / 128, MROWS / 128, 3);
    fp16_gemm<<<gQKV, 256>>>(hidden, Wq, Wk, Wv, q, k, v, 1);

    rope_apply_kernel<<<(BH * SEQ * 64 + 255) / 256, 256>>>();

    flash_fwd<<<dim3(SEQ / 64, BH), 128, FLASH_SMEM_BYTES>>>(q, k, v, attn);

    dim3 gO(DMODEL / 128, MROWS / 128, 1);
    fp16_gemm<<<gO, 256>>>(attn, Wo, Wo, Wo, out, out, out, 0);
}

// round 17
// speedup vs baseline: 1.4910x; 1.1158x over previous
#include <cuda_runtime.h>
#include <cuda_fp16.h>
#include <math.h>
#include <stdint.h>

#define BSZ    2
#define SEQ    2048
#define DMODEL 2048
#define NHEADS 16
#define HDIM   128
#define BH     (BSZ*NHEADS)
#define MROWS  (BSZ*SEQ)

// ---- scratch ----
__device__ float g_q[BH*SEQ*HDIM];
__device__ float g_k[BH*SEQ*HDIM];
__device__ float g_v[BH*SEQ*HDIM];
__device__ float g_attn[MROWS*DMODEL];
__device__ float g_cos[SEQ*64];
__device__ float g_sin[SEQ*64];

__device__ __forceinline__ float to_tf32(float x) {
    float y;
    asm("cvt.rna.tf32.f32 %0, %1;" : "=f"(y) : "f"(x));
    return y;
}
__device__ __forceinline__ void mma_f16(float* c, const uint32_t* a, const uint32_t* b) {
    asm volatile(
        "mma.sync.aligned.m16n8k16.row.col.f32.f16.f16.f32 "
        "{%0,%1,%2,%3}, {%4,%5,%6,%7}, {%8,%9}, {%0,%1,%2,%3};"
        : "+f"(c[0]), "+f"(c[1]), "+f"(c[2]), "+f"(c[3])
        : "r"(a[0]), "r"(a[1]), "r"(a[2]), "r"(a[3]), "r"(b[0]), "r"(b[1]));
}
__device__ __forceinline__ uint32_t pack_h2(float x, float y) {
    __half2 h = __floats2half2_rn(x, y);
    return *(uint32_t*)&h;
}

// =================== RoPE ===================
__global__ void rope_cache_kernel() {
    int idx = blockIdx.x * blockDim.x + threadIdx.x;
    if (idx >= SEQ * 64) return;
    int pos = idx >> 6, j = idx & 63;
    double e    = (double)(2 * j) / 128.0;
    double invf = pow(10000.0, -e);
    double ang  = (double)pos * invf;
    g_cos[idx] = (float)cos(ang);
    g_sin[idx] = (float)sin(ang);
}
__global__ void rope_apply_kernel() {
    int idx = blockIdx.x * blockDim.x + threadIdx.x;
    if (idx >= BH * SEQ * 64) return;
    int j = idx & 63, row = idx >> 6, s = row & (SEQ - 1);
    float c = g_cos[s * 64 + j], sn = g_sin[s * 64 + j];
    float* qp = g_q + (size_t)row * HDIM;
    float* kp = g_k + (size_t)row * HDIM;
    float q1 = qp[j], q2 = qp[j + 64];
    qp[j]      = q1 * c - q2 * sn;
    qp[j + 64] = q2 * c + q1 * sn;
    float k1 = kp[j], k2 = kp[j + 64];
    kp[j]      = k1 * c - k2 * sn;
    kp[j + 64] = k2 * c + k1 * sn;
}

// =================== FP16 GEMM (R15, proven) ===================
#define GEMM_K  DMODEL
#define KSTAGES (GEMM_K / 16)    // 128
#define ATS 132
#define BTS 66
#define A_STAGE (8*ATS)          // 1056 words
#define B_STAGE (16*BTS)         // 1056 words

__global__ __launch_bounds__(256, 2)
void fp16_gemm(const float* __restrict__ A,
               const float* __restrict__ B0, const float* __restrict__ B1,
               const float* __restrict__ B2,
               float* __restrict__ C0, float* __restrict__ C1, float* __restrict__ C2,
               int mode)
{
    __shared__ uint32_t As[2][A_STAGE];
    __shared__ uint32_t Bs[2][B_STAGE];

    const int z = blockIdx.z;
    const float* B = (z == 0) ? B0 : (z == 1) ? B1 : B2;
    float* C       = (z == 0) ? C0 : (z == 1) ? C1 : C2;

    const int tid  = threadIdx.x;
    const int wid  = tid >> 5;
    const int lane = tid & 31;
    const int bm = blockIdx.y * 128;
    const int bn = blockIdx.x * 128;
    const int wm = wid >> 2;
    const int wn = wid & 3;
    const int swzL = lane ^ ((lane >> 3) & 3);

    int aWord[2][2], bWord[2][2];
    const float4* Ap[2];
    const float4* Bp[2];
#pragma unroll
    for (int i = 0; i < 2; i++) {
        int f = i * 256 + tid;
        int row = f >> 2, c4 = f & 3;
        int g = row & 7, hi = (row >> 3) & 1;
        int mt = row >> 4, nt = row >> 3;
        int sw = (g >> 1) & 3;
        int khalf = c4 >> 1;
#pragma unroll
        for (int d = 0; d < 2; d++) {
            int p = 2 * c4 + d;
            int tig = p & 3;
            aWord[i][d] = mt * ATS + 4 * (4 * g + (tig ^ sw)) + (hi + 2 * khalf);
            bWord[i][d] = nt * BTS + 2 * (4 * g + (tig ^ sw)) + khalf;
        }
        Ap[i] = (const float4*)(A + (size_t)(bm + row) * GEMM_K) + c4;
        Bp[i] = (const float4*)(B + (size_t)(bn + row) * GEMM_K) + c4;
    }

    float acc[4][4][4];
#pragma unroll
    for (int mt = 0; mt < 4; mt++)
#pragma unroll
        for (int nt = 0; nt < 4; nt++)
#pragma unroll
            for (int e = 0; e < 4; e++) acc[mt][nt][e] = 0.f;

    float4 pa[2], pb[2];
#pragma unroll
    for (int i = 0; i < 2; i++) { pa[i] = Ap[i][0]; pb[i] = Bp[i][0]; }
#pragma unroll
    for (int i = 0; i < 2; i++) {
        As[0][aWord[i][0]] = pack_h2(pa[i].x, pa[i].y);
        As[0][aWord[i][1]] = pack_h2(pa[i].z, pa[i].w);
        Bs[0][bWord[i][0]] = pack_h2(pb[i].x, pb[i].y);
        Bs[0][bWord[i][1]] = pack_h2(pb[i].z, pb[i].w);
    }
#pragma unroll
    for (int i = 0; i < 2; i++) { pa[i] = Ap[i][4]; pb[i] = Bp[i][4]; }
    __syncthreads();

    const int aT0 = (wm * 4) * ATS + 4 * swzL;
    const int bT0 = (wn * 4) * BTS + 2 * swzL;

#pragma unroll 1
    for (int ks = 0; ks < KSTAGES; ks++) {
        const int buf = ks & 1;
        if (ks + 1 < KSTAGES) {
#pragma unroll
            for (int i = 0; i < 2; i++) {
                As[buf ^ 1][aWord[i][0]] = pack_h2(pa[i].x, pa[i].y);
                As[buf ^ 1][aWord[i][1]] = pack_h2(pa[i].z, pa[i].w);
                Bs[buf ^ 1][bWord[i][0]] = pack_h2(pb[i].x, pb[i].y);
                Bs[buf ^ 1][bWord[i][1]] = pack_h2(pb[i].z, pb[i].w);
            }
        }
        {
            uint32_t a[4][4], b[4][2];
#pragma unroll
            for (int mt = 0; mt < 4; mt++)
                *(uint4*)a[mt] = *(const uint4*)&As[buf][aT0 + mt * ATS];
#pragma unroll
            for (int nt = 0; nt < 4; nt++)
                *(uint2*)b[nt] = *(const uint2*)&Bs[buf][bT0 + nt * BTS];
#pragma unroll
            for (int mt = 0; mt < 4; mt++)
#pragma unroll
                for (int nt = 0; nt < 4; nt++)
                    mma_f16(acc[mt][nt], a[mt], b[nt]);
        }
        if (ks + 2 < KSTAGES) {
#pragma unroll
            for (int i = 0; i < 2; i++) {
                pa[i] = Ap[i][(ks + 2) * 4];
                pb[i] = Bp[i][(ks + 2) * 4];
            }
        }
        __syncthreads();
    }

    const int g = lane >> 2, tig = lane & 3;
#pragma unroll
    for (int mt = 0; mt < 4; mt++) {
#pragma unroll
        for (int nt = 0; nt < 4; nt++) {
            int row = bm + wm * 64 + mt * 16 + g;
            int col = bn + wn * 32 + nt * 8 + tig * 2;
            float* c0;
            size_t rstride;
            if (mode == 0) {
                c0 = C + (size_t)row * DMODEL + col;
                rstride = DMODEL;
            } else {
                int b = row >> 11, s = row & (SEQ - 1);
                int h = col >> 7, hd = col & 127;
                c0 = C + (((size_t)(b * NHEADS + h)) * SEQ + s) * HDIM + hd;
                rstride = HDIM;
            }
            *(float2*)c0 = make_float2(acc[mt][nt][0], acc[mt][nt][1]);
            *(float2*)(c0 + 8 * rstride) = make_float2(acc[mt][nt][2], acc[mt][nt][3]);
        }
    }
}

// =================== Flash attention: fp16 mma, register-resident P ===================
// 64 q-rows/CTA, 128 threads, 2 CTAs/SM.
// K smem (packed half2 along head-dim pairs), word(kv n, hdpair kp):
//   slot = (n>>3)*576 + (kp>>3)*72 + ((kp&7)>>2)*36 + (n&7)*4 + (kp&3)
//   consumer S-mma (nt, kt): b0 = Kh[nt*576 + kt*72 + lane], b1 = +36   (conflict-free)
// V smem (packed half2 along kv pairs), word(hd n, kvpair p):
//   slot = (n>>3)*289 + (p>>3)*72 + ((p&7)>>2)*36 + (n&7)*4 + (p&3)
//   consumer PV (nt, kp): b0 = Vh[nt*289 + kp*72 + lane], b1 = +36      (conflict-free)
// QK^T accumulator cols are TRUE kv pairs {2tig, 2tig+1}; PV a-frag packs them directly.
#define FKOFF_V 4608
#define FLASH_SMEM_BYTES ((4608 + 4624) * 4)   // 36928 B per CTA

__global__ __launch_bounds__(128, 2)
void flash_fwd(const float* __restrict__ Qg, const float* __restrict__ Kg,
               const float* __restrict__ Vg, float* __restrict__ Og)
{
    extern __shared__ uint32_t smu[];
    uint32_t* Kh = smu;
    uint32_t* Vh = smu + FKOFF_V;

    const int tid  = threadIdx.x;
    const int wid  = tid >> 5;            // 0..3
    const int lane = tid & 31;
    const int g4 = lane >> 2, tig = lane & 3;
    const int qt = (int)(gridDim.x - 1 - blockIdx.x);   // heavy CTAs first
    const int bh = blockIdx.y;
    const int m0 = qt * 64;
    const int warpRow = m0 + wid * 16;
    const size_t base = (size_t)bh * SEQ * HDIM;
    const float scale = 0.08838834764831845f;

    // ---- Q a-fragments in registers (packed half2, scale folded) ----
    uint32_t qa[8][4];
    {
        const float2* qA2 = (const float2*)(Qg + base + (size_t)(warpRow + g4) * HDIM);
        const float2* qB2 = (const float2*)(Qg + base + (size_t)(warpRow + g4 + 8) * HDIM);
#pragma unroll
        for (int kt = 0; kt < 8; kt++) {
            int p0 = kt * 8 + tig;             // float2 index: hd = 16kt + 2tig
            float2 a0 = qA2[p0], b0 = qB2[p0];
            float2 a1 = qA2[p0 + 4], b1 = qB2[p0 + 4];
            qa[kt][0] = pack_h2(a0.x * scale, a0.y * scale);
            qa[kt][1] = pack_h2(b0.x * scale, b0.y * scale);
            qa[kt][2] = pack_h2(a1.x * scale, a1.y * scale);
            qa[kt][3] = pack_h2(b1.x * scale, b1.y * scale);
        }
    }

    float o[16][4];
#pragma unroll
    for (int nt = 0; nt < 16; nt++)
#pragma unroll
        for (int e = 0; e < 4; e++) o[nt][e] = 0.f;
    float mA = -1e30f, mB = -1e30f, lA = 0.f, lB = 0.f;

    const int ntiles = qt + 1;
    for (int t = 0; t < ntiles; t++) {
        const int n0 = t * 64;
        __syncthreads();

        // ---- fill K (half2 along hd) ----
#pragma unroll
        for (int i = 0; i < 16; i++) {
            int row = i * 4 + wid;             // kv 0..63
            float4 kv4 = *(const float4*)(Kg + base + (size_t)(n0 + row) * HDIM + lane * 4);
            int slot = (row >> 3) * 576 + (lane >> 2) * 72 + ((lane >> 1) & 1) * 36
                     + (row & 7) * 4 + 2 * (lane & 1);
            *(uint2*)&Kh[slot] = make_uint2(pack_h2(kv4.x, kv4.y), pack_h2(kv4.z, kv4.w));
        }
        // ---- fill V (half2 along kv pairs) ----
#pragma unroll
        for (int i = 0; i < 8; i++) {
            int p = i * 4 + wid;               // kv pair 0..31
            const float* r0 = Vg + base + (size_t)(n0 + 2 * p) * HDIM + lane * 4;
            float4 v0 = *(const float4*)r0;
            float4 v1 = *(const float4*)(r0 + HDIM);
            int sb = (lane >> 1) * 289 + (p >> 3) * 72 + ((p & 7) >> 2) * 36
                   + 16 * (lane & 1) + (p & 3);
            Vh[sb + 0]  = pack_h2(v0.x, v1.x);
            Vh[sb + 4]  = pack_h2(v0.y, v1.y);
            Vh[sb + 8]  = pack_h2(v0.z, v1.z);
            Vh[sb + 12] = pack_h2(v0.w, v1.w);
        }
        __syncthreads();

        // ---- S = Q K^T (fp16 m16n8k16) ----
        float s[8][4];
#pragma unroll
        for (int nt = 0; nt < 8; nt++)
#pragma unroll
            for (int e = 0; e < 4; e++) s[nt][e] = 0.f;
#pragma unroll
        for (int kt = 0; kt < 8; kt++) {
            uint32_t bf[8][2];
#pragma unroll
            for (int nt = 0; nt < 8; nt++) {
                bf[nt][0] = Kh[nt * 576 + kt * 72 + lane];
                bf[nt][1] = Kh[nt * 576 + kt * 72 + 36 + lane];
            }
#pragma unroll
            for (int nt = 0; nt < 8; nt++)
                mma_f16(s[nt], qa[kt], bf[nt]);
        }

        // ---- causal mask (accumulator cols = true kv 2tig, 2tig+1) ----
        const int qrA = warpRow + g4, qrB = qrA + 8;
        if (n0 + 63 > warpRow) {
#pragma unroll
            for (int nt = 0; nt < 8; nt++) {
                int kv0 = n0 + nt * 8 + 2 * tig, kv1 = kv0 + 1;
                if (kv0 > qrA) s[nt][0] = -1e30f;
                if (kv1 > qrA) s[nt][1] = -1e30f;
                if (kv0 > qrB) s[nt][2] = -1e30f;
                if (kv1 > qrB) s[nt][3] = -1e30f;
            }
        }

        // ---- online softmax ----
        float mxA = -1e30f, mxB = -1e30f;
#pragma unroll
        for (int nt = 0; nt < 8; nt++) {
            mxA = fmaxf(mxA, fmaxf(s[nt][0], s[nt][1]));
            mxB = fmaxf(mxB, fmaxf(s[nt][2], s[nt][3]));
        }
        mxA = fmaxf(mxA, __shfl_xor_sync(0xFFFFFFFFu, mxA, 1));
        mxA = fmaxf(mxA, __shfl_xor_sync(0xFFFFFFFFu, mxA, 2));
        mxB = fmaxf(mxB, __shfl_xor_sync(0xFFFFFFFFu, mxB, 1));
        mxB = fmaxf(mxB, __shfl_xor_sync(0xFFFFFFFFu, mxB, 2));
        float mnA = fmaxf(mA, mxA), mnB = fmaxf(mB, mxB);
        float aAl = __expf(mA - mnA), aBl = __expf(mB - mnB);
        mA = mnA; mB = mnB;
#pragma unroll
        for (int nt = 0; nt < 16; nt++) {
            o[nt][0] *= aAl; o[nt][1] *= aAl;
            o[nt][2] *= aBl; o[nt][3] *= aBl;
        }
        float sumA = 0.f, sumB = 0.f;
#pragma unroll
        for (int nt = 0; nt < 8; nt++) {
            float p0 = __expf(s[nt][0] - mA);
            float p1 = __expf(s[nt][1] - mA);
            float p2 = __expf(s[nt][2] - mB);
            float p3 = __expf(s[nt][3] - mB);
            s[nt][0] = p0; s[nt][1] = p1; s[nt][2] = p2; s[nt][3] = p3;
            sumA += p0 + p1; sumB += p2 + p3;
        }
        lA = lA * aAl + sumA;
        lB = lB * aBl + sumB;

        // ---- O += P V  (accumulator pairs pack directly into fp16 a-frags) ----
#pragma unroll
        for (int kp = 0; kp < 4; kp++) {
            uint32_t a[4] = {
                pack_h2(s[2 * kp][0],     s[2 * kp][1]),
                pack_h2(s[2 * kp][2],     s[2 * kp][3]),
                pack_h2(s[2 * kp + 1][0], s[2 * kp + 1][1]),
                pack_h2(s[2 * kp + 1][2], s[2 * kp + 1][3])
            };
            uint32_t bf[16][2];
#pragma unroll
            for (int nt = 0; nt < 16; nt++) {
                bf[nt][0] = Vh[nt * 289 + kp * 72 + lane];
                bf[nt][1] = Vh[nt * 289 + kp * 72 + 36 + lane];
            }
#pragma unroll
            for (int nt = 0; nt < 16; nt++)
                mma_f16(o[nt], a, bf[nt]);
        }
    }

    // ---- epilogue ----
    lA += __shfl_xor_sync(0xFFFFFFFFu, lA, 1);
    lA += __shfl_xor_sync(0xFFFFFFFFu, lA, 2);
    lB += __shfl_xor_sync(0xFFFFFFFFu, lB, 1);
    lB += __shfl_xor_sync(0xFFFFFFFFu, lB, 2);
    float invA = 1.f / lA, invB = 1.f / lB;
    const int b_ = bh >> 4, h = bh & 15;
    const int srA = warpRow + g4, srB = srA + 8;
    float* opA = Og + ((size_t)(b_ * SEQ + srA)) * DMODEL + h * HDIM;
    float* opB = Og + ((size_t)(b_ * SEQ + srB)) * DMODEL + h * HDIM;
#pragma unroll
    for (int nt = 0; nt < 16; nt++) {
        *(float2*)(opA + nt * 8 + 2 * tig) = make_float2(o[nt][0] * invA, o[nt][1] * invA);
        *(float2*)(opB + nt * 8 + 2 * tig) = make_float2(o[nt][2] * invB, o[nt][3] * invB);
    }
}

// =================== launch ===================
extern "C" void kernel_launch(void* const* d_in, const int* in_sizes, int n_in,
                              void* d_out, int out_size)
{
    (void)in_sizes; (void)n_in; (void)out_size;
    const float* hidden = (const float*)d_in[0];
    const float* Wq = (const float*)d_in[3];
    const float* Wk = (const float*)d_in[4];
    const float* Wv = (const float*)d_in[5];
    const float* Wo = (const float*)d_in[6];
    float* out = (float*)d_out;

    float *q, *k, *v, *attn;
    cudaGetSymbolAddress((void**)&q,    g_q);
    cudaGetSymbolAddress((void**)&k,    g_k);
    cudaGetSymbolAddress((void**)&v,    g_v);
    cudaGetSymbolAddress((void**)&attn, g_attn);

    cudaFuncSetAttribute(flash_fwd, cudaFuncAttributeMaxDynamicSharedMemorySize,
                         FLASH_SMEM_BYTES);

    rope_cache_kernel<<<(SEQ * 64 + 255) / 256, 256>>>();

    dim3 gQKV(DMODEL / 128, MROWS / 128, 3);
    fp16_gemm<<<gQKV, 256>>>(hidden, Wq, Wk, Wv, q, k, v, 1);

    rope_apply_kernel<<<(BH * SEQ * 64 + 255) / 256, 256>>>();

    flash_fwd<<<dim3(SEQ / 64, BH), 128, FLASH_SMEM_BYTES>>>(q, k, v, attn);

    dim3 gO(DMODEL / 128, MROWS / 128, 1);
    fp16_gemm<<<gO, 256>>>(attn, Wo, Wo, Wo, out, out, out, 0);
}